// round 6
// baseline (speedup 1.0000x reference)
#include <cuda_runtime.h>
#include <math.h>

// ---------------- problem constants ----------------
#define BATCH   8
#define NSITES  1024
#define ZWD     8
#define ZID     32
#define KOBJ    48
#define CFD     32
#define CROPSZ  28
#define FAN     (CFD*CROPSZ*CROPSZ)   // 25088
#define MTOT    (KOBJ*BATCH)          // 384
#define WRAW    128
#define PIX     (WRAW*WRAW)           // 16384
#define SMALLF  (2*CROPSZ*CROPSZ)     // 1568
#define NSPLIT  98

// ---------------- output offsets ----------------
#define OFF_PROBMAP  0u
#define OFF_AREAMAP  8192u
#define OFF_CFEW     16384u
#define OFF_PFEW     16768u
#define OFF_BXF      17152u
#define OFF_BYF      17536u
#define OFF_BWF      17920u
#define OFF_BHF      18304u
#define OFF_BMASK    18688u
#define OFF_BMNON    6310144u
#define OFF_BIMG     12601600u
#define OFF_ZSF      18893056u
#define OFF_ZKF      18896128u
#define OFF_ZIS      18899200u
#define OFF_ZIK      18911488u

// ---------------- device scratch ----------------
__device__ float g_zs   [NSITES*BATCH*ZWD];
__device__ float g_zkl  [NSITES*BATCH*ZWD];
__device__ float g_bx   [NSITES*BATCH];
__device__ float g_by   [NSITES*BATCH];
__device__ float g_bw   [NSITES*BATCH];
__device__ float g_bh   [NSITES*BATCH];
__device__ float g_call [NSITES*BATCH];
__device__ float g_bxf  [MTOT];
__device__ float g_byf  [MTOT];
__device__ float g_bwf  [MTOT];
__device__ float g_bhf  [MTOT];
__device__ float g_cf   [MTOT];
__device__ float g_crop [MTOT*FAN];          // 9.63M floats
__device__ float g_encp [NSPLIT*MTOT*64];    // GEMM partials
__device__ float g_smallw[MTOT*SMALLF];

// ---------------- helpers ----------------
__device__ __forceinline__ float sigmoidf_(float x){ return 1.0f/(1.0f+expf(-x)); }
__device__ __forceinline__ float softplusf_(float x){ return fmaxf(x,0.0f) + log1pf(expf(-fabsf(x))); }

// ================= K1: per-site zwhere sample/kl, tmaps, boxes, prob/area =================
__global__ void k1_site(const float* __restrict__ logit,
                        const float* __restrict__ zmu,
                        const float* __restrict__ zstd,
                        const float* __restrict__ zeps,
                        const float* __restrict__ wz,
                        const float* __restrict__ bz,
                        float* __restrict__ out)
{
    int g = blockIdx.x*blockDim.x + threadIdx.x;
    if (g >= BATCH*NSITES) return;
    int b = g >> 10;
    int n = g & 1023;

    float zs[ZWD];
    #pragma unroll
    for (int z = 0; z < ZWD; z++) {
        int idx = (b*ZWD + z)*NSITES + n;
        float mu = zmu[idx];
        float sd = zstd[idx];
        float s  = mu + sd * zeps[idx];
        float kl = 0.5f*(mu*mu + sd*sd) - logf(sd) - 0.5f;
        zs[z] = s;
        g_zs [(n*BATCH+b)*ZWD + z] = s;
        g_zkl[(n*BATCH+b)*ZWD + z] = kl;
    }

    float t[4];
    #pragma unroll
    for (int c = 0; c < 4; c++) {
        float a = __ldg(&bz[c]);
        #pragma unroll
        for (int z = 0; z < ZWD; z++) a += zs[z]*__ldg(&wz[c*ZWD+z]);
        t[c] = sigmoidf_(a);
    }
    int ix = n >> 5, iy = n & 31;
    float bx = 4.0f*((float)ix + t[0]);
    float by = 4.0f*((float)iy + t[1]);
    float bw = 10.0f + 30.0f*t[2];
    float bh = 10.0f + 30.0f*t[3];
    g_bx[n*BATCH+b] = bx;  g_by[n*BATCH+b] = by;
    g_bw[n*BATCH+b] = bw;  g_bh[n*BATCH+b] = bh;

    out[OFF_AREAMAP + b*NSITES + n] = bw*bh;
    float c0 = logit[b*NSITES + n];
    out[OFF_PROBMAP + b*NSITES + n] = sigmoidf_(c0);
    g_call[n*BATCH+b] = c0;
}

// ================= K2: per-batch top-48 (shuffle) + gathers =================
__global__ void __launch_bounds__(1024) k2_topk(float* __restrict__ out)
{
    int b = blockIdx.x, t = threadIdx.x;
    int lane = t & 31, wid = t >> 5;
    __shared__ float wv[32];
    __shared__ int   wi[32];
    __shared__ int   win[KOBJ];

    float v = g_call[t*BATCH + b];

    for (int kk = 0; kk < KOBJ; kk++) {
        float bv = v; int bi = t;
        #pragma unroll
        for (int o = 16; o > 0; o >>= 1) {
            float ov = __shfl_down_sync(0xffffffffu, bv, o);
            int   oi = __shfl_down_sync(0xffffffffu, bi, o);
            if (ov > bv || (ov == bv && oi < bi)) { bv = ov; bi = oi; }
        }
        if (lane == 0) { wv[wid] = bv; wi[wid] = bi; }
        __syncthreads();
        if (wid == 0) {
            bv = wv[lane]; bi = wi[lane];
            #pragma unroll
            for (int o = 16; o > 0; o >>= 1) {
                float ov = __shfl_down_sync(0xffffffffu, bv, o);
                int   oi = __shfl_down_sync(0xffffffffu, bi, o);
                if (ov > bv || (ov == bv && oi < bi)) { bv = ov; bi = oi; }
            }
            if (lane == 0) win[kk] = bi;
        }
        __syncthreads();
        if (t == win[kk]) v = -1e30f;
    }

    if (t < KOBJ) {
        int kk = t, n = win[kk];
        int m = kk*BATCH + b;
        float c = g_call[n*BATCH+b];
        out[OFF_CFEW + m] = c;
        out[OFF_PFEW + m] = sigmoidf_(c);
        float bx = g_bx[n*BATCH+b], by = g_by[n*BATCH+b];
        float bw = g_bw[n*BATCH+b], bh = g_bh[n*BATCH+b];
        out[OFF_BXF + m] = bx;  out[OFF_BYF + m] = by;
        out[OFF_BWF + m] = bw;  out[OFF_BHF + m] = bh;
        g_bxf[m] = bx; g_byf[m] = by; g_bwf[m] = bw; g_bhf[m] = bh;
        g_cf[m] = c;
        #pragma unroll
        for (int z = 0; z < ZWD; z++) {
            out[OFF_ZSF + m*ZWD + z] = g_zs [(n*BATCH+b)*ZWD + z];
            out[OFF_ZKF + m*ZWD + z] = g_zkl[(n*BATCH+b)*ZWD + z];
        }
    }
}

// ================= K3: bilinear crop -> g_crop (precomputed sample table) ===========
__global__ void __launch_bounds__(256) k3_crop(const float* __restrict__ feat)
{
    int m = blockIdx.x;
    int b = m & 7;
    int t = threadIdx.x;
    __shared__ int   si0[784], si1[784], si2[784], si3[784];
    __shared__ float sw0[784], sw1[784], sw2[784], sw3[784];

    float bx = g_bxf[m], bw = g_bwf[m];
    float by = g_byf[m], bh = g_bhf[m];

    for (int pos = t; pos < 784; pos += 256) {
        int i = pos / 28, j = pos - (pos/28)*28;
        float u = ((float)i + 0.5f) / 28.0f;
        float vv= ((float)j + 0.5f) / 28.0f;
        float x = bx + (u - 0.5f)*bw - 0.5f;
        float y = by + (vv- 0.5f)*bh - 0.5f;
        float x0f = floorf(x), y0f = floorf(y);
        int x0 = (int)x0f, y0 = (int)y0f;
        float wx1 = x - x0f, wy1 = y - y0f;
        float wx0 = 1.0f - wx1, wy0 = 1.0f - wy1;
        bool xa = (x0   >= 0 && x0   < WRAW);
        bool xb = (x0+1 >= 0 && x0+1 < WRAW);
        bool ya = (y0   >= 0 && y0   < WRAW);
        bool yb = (y0+1 >= 0 && y0+1 < WRAW);
        int cx0 = min(max(x0,   0), WRAW-1);
        int cx1 = min(max(x0+1, 0), WRAW-1);
        int cy0 = min(max(y0,   0), WRAW-1);
        int cy1 = min(max(y0+1, 0), WRAW-1);
        si0[pos] = cx0*WRAW + cy0;  sw0[pos] = (xa&&ya) ? wx0*wy0 : 0.0f;
        si1[pos] = cx1*WRAW + cy0;  sw1[pos] = (xb&&ya) ? wx1*wy0 : 0.0f;
        si2[pos] = cx0*WRAW + cy1;  sw2[pos] = (xa&&yb) ? wx0*wy1 : 0.0f;
        si3[pos] = cx1*WRAW + cy1;  sw3[pos] = (xb&&yb) ? wx1*wy1 : 0.0f;
    }
    __syncthreads();

    const float* fb = feat + (size_t)b*CFD*PIX;
    float* dst = &g_crop[(size_t)m*FAN];
    #pragma unroll 2
    for (int c = 0; c < CFD; c++) {
        const float* img = fb + c*PIX;
        for (int pos = t; pos < 784; pos += 256) {
            float v = sw0[pos]*__ldg(&img[si0[pos]])
                    + sw1[pos]*__ldg(&img[si1[pos]])
                    + sw2[pos]*__ldg(&img[si2[pos]])
                    + sw3[pos]*__ldg(&img[si3[pos]]);
            dst[c*784 + pos] = v;
        }
    }
}

// ================= K4: enc GEMM (384 x 64 x 25088), reg-prefetch pipeline ==========
#define KT4   32
#define KITER 8
#define ASTR  33
__global__ void __launch_bounds__(256,2) k4_gemm(const float* __restrict__ wenc)
{
    __shared__ float As[128*ASTR];
    __shared__ float Bs[KT4*64];
    int t = threadIdx.x;
    int mbase = blockIdx.x * 128;
    int kb0   = blockIdx.y * (KITER*KT4);
    int m0 = (t >> 3) * 4;
    int n0 = (t & 7) * 8;
    int ldm = t >> 3;
    int ldk = (t & 7) * 4;
    int dB  = t & 63;
    int kqB = (t >> 6) * 8;

    float acc[4][8];
    #pragma unroll
    for (int i = 0; i < 4; i++)
        #pragma unroll
        for (int j = 0; j < 8; j++) acc[i][j] = 0.0f;

    float4 ra[4], rb0, rb1;
    #pragma unroll
    for (int p = 0; p < 4; p++)
        ra[p] = *(const float4*)&g_crop[(size_t)(mbase + p*32 + ldm)*FAN + kb0 + ldk];
    rb0 = *(const float4*)&wenc[(size_t)dB*FAN + kb0 + kqB];
    rb1 = *(const float4*)&wenc[(size_t)dB*FAN + kb0 + kqB + 4];

    for (int it = 0; it < KITER; it++) {
        #pragma unroll
        for (int p = 0; p < 4; p++) {
            int mm = p*32 + ldm;
            As[mm*ASTR + ldk+0] = ra[p].x;
            As[mm*ASTR + ldk+1] = ra[p].y;
            As[mm*ASTR + ldk+2] = ra[p].z;
            As[mm*ASTR + ldk+3] = ra[p].w;
        }
        Bs[(kqB+0)*64 + dB] = rb0.x;
        Bs[(kqB+1)*64 + dB] = rb0.y;
        Bs[(kqB+2)*64 + dB] = rb0.z;
        Bs[(kqB+3)*64 + dB] = rb0.w;
        Bs[(kqB+4)*64 + dB] = rb1.x;
        Bs[(kqB+5)*64 + dB] = rb1.y;
        Bs[(kqB+6)*64 + dB] = rb1.z;
        Bs[(kqB+7)*64 + dB] = rb1.w;
        __syncthreads();

        if (it + 1 < KITER) {
            int kb = kb0 + (it+1)*KT4;
            #pragma unroll
            for (int p = 0; p < 4; p++)
                ra[p] = *(const float4*)&g_crop[(size_t)(mbase + p*32 + ldm)*FAN + kb + ldk];
            rb0 = *(const float4*)&wenc[(size_t)dB*FAN + kb + kqB];
            rb1 = *(const float4*)&wenc[(size_t)dB*FAN + kb + kqB + 4];
        }

        #pragma unroll 8
        for (int kk = 0; kk < KT4; kk++) {
            float a0 = As[(m0+0)*ASTR + kk];
            float a1 = As[(m0+1)*ASTR + kk];
            float a2 = As[(m0+2)*ASTR + kk];
            float a3 = As[(m0+3)*ASTR + kk];
            float4 b0 = *(const float4*)&Bs[kk*64 + n0];
            float4 b1 = *(const float4*)&Bs[kk*64 + n0 + 4];
            acc[0][0] += a0*b0.x; acc[0][1] += a0*b0.y; acc[0][2] += a0*b0.z; acc[0][3] += a0*b0.w;
            acc[0][4] += a0*b1.x; acc[0][5] += a0*b1.y; acc[0][6] += a0*b1.z; acc[0][7] += a0*b1.w;
            acc[1][0] += a1*b0.x; acc[1][1] += a1*b0.y; acc[1][2] += a1*b0.z; acc[1][3] += a1*b0.w;
            acc[1][4] += a1*b1.x; acc[1][5] += a1*b1.y; acc[1][6] += a1*b1.z; acc[1][7] += a1*b1.w;
            acc[2][0] += a2*b0.x; acc[2][1] += a2*b0.y; acc[2][2] += a2*b0.z; acc[2][3] += a2*b0.w;
            acc[2][4] += a2*b1.x; acc[2][5] += a2*b1.y; acc[2][6] += a2*b1.z; acc[2][7] += a2*b1.w;
            acc[3][0] += a3*b0.x; acc[3][1] += a3*b0.y; acc[3][2] += a3*b0.z; acc[3][3] += a3*b0.w;
            acc[3][4] += a3*b1.x; acc[3][5] += a3*b1.y; acc[3][6] += a3*b1.z; acc[3][7] += a3*b1.w;
        }
        __syncthreads();
    }

    size_t pbase = ((size_t)blockIdx.y*MTOT + mbase + m0)*64 + n0;
    #pragma unroll
    for (int i = 0; i < 4; i++) {
        float4 w0 = make_float4(acc[i][0], acc[i][1], acc[i][2], acc[i][3]);
        float4 w1 = make_float4(acc[i][4], acc[i][5], acc[i][6], acc[i][7]);
        *(float4*)&g_encp[pbase + (size_t)i*64]     = w0;
        *(float4*)&g_encp[pbase + (size_t)i*64 + 4] = w1;
    }
}

// ================= K5: reduce partials + zi sample/kl + dec GEMM + small*c_few ============
__global__ void k5_zi_dec(const float* __restrict__ epszi,
                          const float* __restrict__ wdec,
                          const float* __restrict__ bdec,
                          const float* __restrict__ benc,
                          float* __restrict__ out)
{
    int m = blockIdx.x, t = threadIdx.x;
    __shared__ float zsh[ZID];
    __shared__ float ench[64];
    __shared__ float red[4][64];
    {
        int c = t & 63, part = t >> 6;
        float s = 0.0f;
        int lo = part*24 + min(part,2);   // 25,25,24,24 split of 98
        int hi = lo + ((part < 2) ? 25 : 24);
        for (int sp = lo; sp < hi; sp++)
            s += g_encp[((size_t)sp*MTOT + m)*64 + c];
        red[part][c] = s;
    }
    __syncthreads();
    if (t < 64) ench[t] = benc[t] + red[0][t] + red[1][t] + red[2][t] + red[3][t];
    __syncthreads();
    if (t < ZID) {
        float mu = ench[t];
        float sp = ench[32 + t];
        float sd = softplusf_(sp) + 1e-4f;
        float s  = mu + sd * epszi[m*ZID + t];
        float kl = 0.5f*(mu*mu + sd*sd) - logf(sd) - 0.5f;
        out[OFF_ZIS + m*ZID + t] = s;
        out[OFF_ZIK + m*ZID + t] = kl;
        zsh[t] = s;
    }
    __syncthreads();
    float cf = g_cf[m];
    for (int f = t; f < SMALLF; f += 256) {
        const float4* wr = (const float4*)(wdec + (size_t)f*ZID);
        float acc = bdec[f];
        #pragma unroll
        for (int q = 0; q < 8; q++) {
            float4 w4 = wr[q];
            acc += w4.x*zsh[q*4+0] + w4.y*zsh[q*4+1]
                 + w4.z*zsh[q*4+2] + w4.w*zsh[q*4+3];
        }
        float r = (f < 784) ? softplusf_(acc) : sigmoidf_(acc);
        g_smallw[m*SMALLF + f] = r * cf;
    }
}

// ================= K67: fused weight-uncrop + k-reduction -> big_mask, big_mask_non ======
// grid: 8 batches x 32 tiles of 512 pixels; 256 threads, 2 pixels each.
__global__ void __launch_bounds__(256) k67_mask(float* __restrict__ out)
{
    int blk = blockIdx.x;
    int b = blk >> 5;
    int tile = blk & 31;
    int t = threadIdx.x;
    __shared__ float ssx[KOBJ], sox[KOBJ], ssy[KOBJ], soy[KOBJ];
    if (t < KOBJ) {
        int m = t*BATCH + b;
        float bx = g_bxf[m], bw = g_bwf[m];
        float by = g_byf[m], bh = g_bhf[m];
        float sx = 28.0f / bw;
        float sy = 28.0f / bh;
        ssx[t] = sx;  sox[t] = (0.5f - bx + 0.5f*bw)*sx - 0.5f;
        ssy[t] = sy;  soy[t] = (0.5f - by + 0.5f*bh)*sy - 0.5f;
    }
    __syncthreads();

    #pragma unroll
    for (int pp = 0; pp < 2; pp++) {
        int p = tile*512 + pp*256 + t;
        int X = p >> 7, Y = p & 127;
        float v[KOBJ];
        float s = 0.0f;
        #pragma unroll
        for (int k = 0; k < KOBJ; k++) {
            float x = (float)X*ssx[k] + sox[k];
            float y = (float)Y*ssy[k] + soy[k];
            float w = 0.0f;
            if (x > -1.0f && x < 28.0f && y > -1.0f && y < 28.0f) {
                float x0f = floorf(x), y0f = floorf(y);
                int x0 = (int)x0f, y0 = (int)y0f;
                float wx1 = x - x0f, wy1 = y - y0f;
                float wx0 = 1.0f - wx1, wy0 = 1.0f - wy1;
                bool xa = (x0 >= 0), xb = (x0+1 < 28);
                bool ya = (y0 >= 0), yb = (y0+1 < 28);
                const float* img = &g_smallw[(size_t)(k*BATCH+b)*SMALLF];
                int i00 = x0*28 + y0;
                float v00 = (xa&&ya) ? __ldg(&img[i00])    : 0.0f;
                float v10 = (xb&&ya) ? __ldg(&img[i00+28]) : 0.0f;
                float v01 = (xa&&yb) ? __ldg(&img[i00+1])  : 0.0f;
                float v11 = (xb&&yb) ? __ldg(&img[i00+29]) : 0.0f;
                w = v00*wx0*wy0 + v10*wx1*wy0 + v01*wx0*wy1 + v11*wx1*wy1;
            }
            v[k] = w;
            s += w;
            out[OFF_BMNON + (size_t)(k*BATCH+b)*PIX + p] = tanhf(w);
        }
        float ts = tanhf(s);
        float inv = 1.0f / fmaxf(s, 1e-6f);
        #pragma unroll
        for (int k = 0; k < KOBJ; k++)
            out[OFF_BMASK + (size_t)(k*BATCH+b)*PIX + p] = ts * (v[k] * inv);
    }
}

// ================= K6b: img-channel uncrop -> big_img =================
__global__ void __launch_bounds__(256) k6b_img(float* __restrict__ out)
{
    int m = blockIdx.x, t = threadIdx.x;
    __shared__ float sm[784];
    __shared__ float xs[WRAW], ys[WRAW];
    for (int i = t; i < 784; i += 256) sm[i] = g_smallw[(size_t)m*SMALLF + 784 + i];
    if (t < WRAW) {
        float bx = g_bxf[m], bw = g_bwf[m];
        float by = g_byf[m], bh = g_bhf[m];
        xs[t] = ((float)t + 0.5f - (bx - 0.5f*bw)) / bw * 28.0f - 0.5f;
        ys[t] = ((float)t + 0.5f - (by - 0.5f*bh)) / bh * 28.0f - 0.5f;
    }
    __syncthreads();
    size_t base = (size_t)m * PIX;
    for (int p = t; p < PIX; p += 256) {
        int X = p >> 7, Y = p & 127;
        float x = xs[X], y = ys[Y];
        float im = 0.0f;
        if (x > -1.0f && x < 28.0f && y > -1.0f && y < 28.0f) {
            float x0f = floorf(x), y0f = floorf(y);
            int x0 = (int)x0f, y0 = (int)y0f;
            float wx1 = x - x0f, wy1 = y - y0f;
            float wx0 = 1.0f - wx1, wy0 = 1.0f - wy1;
            bool xa = (x0 >= 0), xb = (x0+1 < 28);
            bool ya = (y0 >= 0), yb = (y0+1 < 28);
            int i00 = x0*28 + y0;
            float v00 = (xa&&ya) ? sm[i00]    : 0.0f;
            float v10 = (xb&&ya) ? sm[i00+28] : 0.0f;
            float v01 = (xa&&yb) ? sm[i00+1]  : 0.0f;
            float v11 = (xb&&yb) ? sm[i00+29] : 0.0f;
            im = v00*wx0*wy0 + v10*wx1*wy0 + v01*wx0*wy1 + v11*wx1*wy1;
        }
        out[OFF_BIMG + base + p] = im;
    }
}

// ================= launcher =================
extern "C" void kernel_launch(void* const* d_in, const int* in_sizes, int n_in,
                              void* d_out, int out_size)
{
    const float* logit = (const float*)d_in[0];
    const float* zmu   = (const float*)d_in[1];
    const float* zstd  = (const float*)d_in[2];
    const float* zeps  = (const float*)d_in[3];
    const float* epszi = (const float*)d_in[4];
    const float* feat  = (const float*)d_in[5];
    const float* wz    = (const float*)d_in[6];
    const float* bz    = (const float*)d_in[7];
    const float* wenc  = (const float*)d_in[8];
    const float* benc  = (const float*)d_in[9];
    const float* wdec  = (const float*)d_in[10];
    const float* bdec  = (const float*)d_in[11];
    float* out = (float*)d_out;

    k1_site<<<32, 256>>>(logit, zmu, zstd, zeps, wz, bz, out);
    k2_topk<<<BATCH, 1024>>>(out);
    k3_crop<<<MTOT, 256>>>(feat);
    dim3 g4(3, NSPLIT);
    k4_gemm<<<g4, 256>>>(wenc);
    k5_zi_dec<<<MTOT, 256>>>(epszi, wdec, bdec, benc, out);
    k67_mask<<<BATCH*32, 256>>>(out);
    k6b_img<<<MTOT, 256>>>(out);
}

// round 7
// speedup vs baseline: 1.0953x; 1.0953x over previous
#include <cuda_runtime.h>
#include <math.h>

// ---------------- problem constants ----------------
#define BATCH   8
#define NSITES  1024
#define ZWD     8
#define ZID     32
#define KOBJ    48
#define CFD     32
#define CROPSZ  28
#define FAN     (CFD*CROPSZ*CROPSZ)   // 25088
#define MTOT    (KOBJ*BATCH)          // 384
#define WRAW    128
#define PIX     (WRAW*WRAW)           // 16384
#define SMALLF  (2*CROPSZ*CROPSZ)     // 1568
#define NSPLIT  98

// ---------------- output offsets ----------------
#define OFF_PROBMAP  0u
#define OFF_AREAMAP  8192u
#define OFF_CFEW     16384u
#define OFF_PFEW     16768u
#define OFF_BXF      17152u
#define OFF_BYF      17536u
#define OFF_BWF      17920u
#define OFF_BHF      18304u
#define OFF_BMASK    18688u
#define OFF_BMNON    6310144u
#define OFF_BIMG     12601600u
#define OFF_ZSF      18893056u
#define OFF_ZKF      18896128u
#define OFF_ZIS      18899200u
#define OFF_ZIK      18911488u

// ---------------- device scratch ----------------
__device__ float g_zs   [NSITES*BATCH*ZWD];
__device__ float g_zkl  [NSITES*BATCH*ZWD];
__device__ float g_bx   [NSITES*BATCH];
__device__ float g_by   [NSITES*BATCH];
__device__ float g_bw   [NSITES*BATCH];
__device__ float g_bh   [NSITES*BATCH];
__device__ float g_call [NSITES*BATCH];
__device__ float g_bxf  [MTOT];
__device__ float g_byf  [MTOT];
__device__ float g_bwf  [MTOT];
__device__ float g_bhf  [MTOT];
__device__ float g_cf   [MTOT];
__device__ float g_crop [MTOT*FAN];          // 9.63M floats
__device__ float g_encp [NSPLIT*MTOT*64];    // GEMM partials
__device__ float g_smallw[MTOT*SMALLF];

// ---------------- helpers ----------------
__device__ __forceinline__ float sigmoidf_(float x){ return 1.0f/(1.0f+expf(-x)); }
__device__ __forceinline__ float softplusf_(float x){ return fmaxf(x,0.0f) + log1pf(expf(-fabsf(x))); }

// ================= K1: per-site zwhere sample/kl, tmaps, boxes, prob/area =================
__global__ void k1_site(const float* __restrict__ logit,
                        const float* __restrict__ zmu,
                        const float* __restrict__ zstd,
                        const float* __restrict__ zeps,
                        const float* __restrict__ wz,
                        const float* __restrict__ bz,
                        float* __restrict__ out)
{
    int g = blockIdx.x*blockDim.x + threadIdx.x;
    if (g >= BATCH*NSITES) return;
    int b = g >> 10;
    int n = g & 1023;

    float zs[ZWD];
    #pragma unroll
    for (int z = 0; z < ZWD; z++) {
        int idx = (b*ZWD + z)*NSITES + n;
        float mu = zmu[idx];
        float sd = zstd[idx];
        float s  = mu + sd * zeps[idx];
        float kl = 0.5f*(mu*mu + sd*sd) - logf(sd) - 0.5f;
        zs[z] = s;
        g_zs [(n*BATCH+b)*ZWD + z] = s;
        g_zkl[(n*BATCH+b)*ZWD + z] = kl;
    }

    float t[4];
    #pragma unroll
    for (int c = 0; c < 4; c++) {
        float a = __ldg(&bz[c]);
        #pragma unroll
        for (int z = 0; z < ZWD; z++) a += zs[z]*__ldg(&wz[c*ZWD+z]);
        t[c] = sigmoidf_(a);
    }
    int ix = n >> 5, iy = n & 31;
    float bx = 4.0f*((float)ix + t[0]);
    float by = 4.0f*((float)iy + t[1]);
    float bw = 10.0f + 30.0f*t[2];
    float bh = 10.0f + 30.0f*t[3];
    g_bx[n*BATCH+b] = bx;  g_by[n*BATCH+b] = by;
    g_bw[n*BATCH+b] = bw;  g_bh[n*BATCH+b] = bh;

    out[OFF_AREAMAP + b*NSITES + n] = bw*bh;
    float c0 = logit[b*NSITES + n];
    out[OFF_PROBMAP + b*NSITES + n] = sigmoidf_(c0);
    g_call[n*BATCH+b] = c0;
}

// ================= K2: per-batch top-48 (shuffle) + gathers =================
__global__ void __launch_bounds__(1024) k2_topk(float* __restrict__ out)
{
    int b = blockIdx.x, t = threadIdx.x;
    int lane = t & 31, wid = t >> 5;
    __shared__ float wv[32];
    __shared__ int   wi[32];
    __shared__ int   win[KOBJ];

    float v = g_call[t*BATCH + b];

    for (int kk = 0; kk < KOBJ; kk++) {
        float bv = v; int bi = t;
        #pragma unroll
        for (int o = 16; o > 0; o >>= 1) {
            float ov = __shfl_down_sync(0xffffffffu, bv, o);
            int   oi = __shfl_down_sync(0xffffffffu, bi, o);
            if (ov > bv || (ov == bv && oi < bi)) { bv = ov; bi = oi; }
        }
        if (lane == 0) { wv[wid] = bv; wi[wid] = bi; }
        __syncthreads();
        if (wid == 0) {
            bv = wv[lane]; bi = wi[lane];
            #pragma unroll
            for (int o = 16; o > 0; o >>= 1) {
                float ov = __shfl_down_sync(0xffffffffu, bv, o);
                int   oi = __shfl_down_sync(0xffffffffu, bi, o);
                if (ov > bv || (ov == bv && oi < bi)) { bv = ov; bi = oi; }
            }
            if (lane == 0) win[kk] = bi;
        }
        __syncthreads();
        if (t == win[kk]) v = -1e30f;
    }

    if (t < KOBJ) {
        int kk = t, n = win[kk];
        int m = kk*BATCH + b;
        float c = g_call[n*BATCH+b];
        out[OFF_CFEW + m] = c;
        out[OFF_PFEW + m] = sigmoidf_(c);
        float bx = g_bx[n*BATCH+b], by = g_by[n*BATCH+b];
        float bw = g_bw[n*BATCH+b], bh = g_bh[n*BATCH+b];
        out[OFF_BXF + m] = bx;  out[OFF_BYF + m] = by;
        out[OFF_BWF + m] = bw;  out[OFF_BHF + m] = bh;
        g_bxf[m] = bx; g_byf[m] = by; g_bwf[m] = bw; g_bhf[m] = bh;
        g_cf[m] = c;
        #pragma unroll
        for (int z = 0; z < ZWD; z++) {
            out[OFF_ZSF + m*ZWD + z] = g_zs [(n*BATCH+b)*ZWD + z];
            out[OFF_ZKF + m*ZWD + z] = g_zkl[(n*BATCH+b)*ZWD + z];
        }
    }
}

// ================= K3: bilinear crop -> g_crop (precomputed sample table) ===========
__global__ void __launch_bounds__(256) k3_crop(const float* __restrict__ feat)
{
    int m = blockIdx.x;
    int b = m & 7;
    int t = threadIdx.x;
    __shared__ int   si0[784], si1[784], si2[784], si3[784];
    __shared__ float sw0[784], sw1[784], sw2[784], sw3[784];

    float bx = g_bxf[m], bw = g_bwf[m];
    float by = g_byf[m], bh = g_bhf[m];

    for (int pos = t; pos < 784; pos += 256) {
        int i = pos / 28, j = pos - (pos/28)*28;
        float u = ((float)i + 0.5f) / 28.0f;
        float vv= ((float)j + 0.5f) / 28.0f;
        float x = bx + (u - 0.5f)*bw - 0.5f;
        float y = by + (vv- 0.5f)*bh - 0.5f;
        float x0f = floorf(x), y0f = floorf(y);
        int x0 = (int)x0f, y0 = (int)y0f;
        float wx1 = x - x0f, wy1 = y - y0f;
        float wx0 = 1.0f - wx1, wy0 = 1.0f - wy1;
        bool xa = (x0   >= 0 && x0   < WRAW);
        bool xb = (x0+1 >= 0 && x0+1 < WRAW);
        bool ya = (y0   >= 0 && y0   < WRAW);
        bool yb = (y0+1 >= 0 && y0+1 < WRAW);
        int cx0 = min(max(x0,   0), WRAW-1);
        int cx1 = min(max(x0+1, 0), WRAW-1);
        int cy0 = min(max(y0,   0), WRAW-1);
        int cy1 = min(max(y0+1, 0), WRAW-1);
        si0[pos] = cx0*WRAW + cy0;  sw0[pos] = (xa&&ya) ? wx0*wy0 : 0.0f;
        si1[pos] = cx1*WRAW + cy0;  sw1[pos] = (xb&&ya) ? wx1*wy0 : 0.0f;
        si2[pos] = cx0*WRAW + cy1;  sw2[pos] = (xa&&yb) ? wx0*wy1 : 0.0f;
        si3[pos] = cx1*WRAW + cy1;  sw3[pos] = (xb&&yb) ? wx1*wy1 : 0.0f;
    }
    __syncthreads();

    const float* fb = feat + (size_t)b*CFD*PIX;
    float* dst = &g_crop[(size_t)m*FAN];
    #pragma unroll 2
    for (int c = 0; c < CFD; c++) {
        const float* img = fb + c*PIX;
        for (int pos = t; pos < 784; pos += 256) {
            float v = sw0[pos]*__ldg(&img[si0[pos]])
                    + sw1[pos]*__ldg(&img[si1[pos]])
                    + sw2[pos]*__ldg(&img[si2[pos]])
                    + sw3[pos]*__ldg(&img[si3[pos]]);
            dst[c*784 + pos] = v;
        }
    }
}

// ================= K4: enc GEMM (384 x 64 x 25088), reg-prefetch pipeline ==========
#define KT4   32
#define KITER 8
#define ASTR  33
__global__ void __launch_bounds__(256,2) k4_gemm(const float* __restrict__ wenc)
{
    __shared__ float As[128*ASTR];
    __shared__ float Bs[KT4*64];
    int t = threadIdx.x;
    int mbase = blockIdx.x * 128;
    int kb0   = blockIdx.y * (KITER*KT4);
    int m0 = (t >> 3) * 4;
    int n0 = (t & 7) * 8;
    int ldm = t >> 3;
    int ldk = (t & 7) * 4;
    int dB  = t & 63;
    int kqB = (t >> 6) * 8;

    float acc[4][8];
    #pragma unroll
    for (int i = 0; i < 4; i++)
        #pragma unroll
        for (int j = 0; j < 8; j++) acc[i][j] = 0.0f;

    float4 ra[4], rb0, rb1;
    #pragma unroll
    for (int p = 0; p < 4; p++)
        ra[p] = *(const float4*)&g_crop[(size_t)(mbase + p*32 + ldm)*FAN + kb0 + ldk];
    rb0 = *(const float4*)&wenc[(size_t)dB*FAN + kb0 + kqB];
    rb1 = *(const float4*)&wenc[(size_t)dB*FAN + kb0 + kqB + 4];

    for (int it = 0; it < KITER; it++) {
        #pragma unroll
        for (int p = 0; p < 4; p++) {
            int mm = p*32 + ldm;
            As[mm*ASTR + ldk+0] = ra[p].x;
            As[mm*ASTR + ldk+1] = ra[p].y;
            As[mm*ASTR + ldk+2] = ra[p].z;
            As[mm*ASTR + ldk+3] = ra[p].w;
        }
        Bs[(kqB+0)*64 + dB] = rb0.x;
        Bs[(kqB+1)*64 + dB] = rb0.y;
        Bs[(kqB+2)*64 + dB] = rb0.z;
        Bs[(kqB+3)*64 + dB] = rb0.w;
        Bs[(kqB+4)*64 + dB] = rb1.x;
        Bs[(kqB+5)*64 + dB] = rb1.y;
        Bs[(kqB+6)*64 + dB] = rb1.z;
        Bs[(kqB+7)*64 + dB] = rb1.w;
        __syncthreads();

        if (it + 1 < KITER) {
            int kb = kb0 + (it+1)*KT4;
            #pragma unroll
            for (int p = 0; p < 4; p++)
                ra[p] = *(const float4*)&g_crop[(size_t)(mbase + p*32 + ldm)*FAN + kb + ldk];
            rb0 = *(const float4*)&wenc[(size_t)dB*FAN + kb + kqB];
            rb1 = *(const float4*)&wenc[(size_t)dB*FAN + kb + kqB + 4];
        }

        #pragma unroll 8
        for (int kk = 0; kk < KT4; kk++) {
            float a0 = As[(m0+0)*ASTR + kk];
            float a1 = As[(m0+1)*ASTR + kk];
            float a2 = As[(m0+2)*ASTR + kk];
            float a3 = As[(m0+3)*ASTR + kk];
            float4 b0 = *(const float4*)&Bs[kk*64 + n0];
            float4 b1 = *(const float4*)&Bs[kk*64 + n0 + 4];
            acc[0][0] += a0*b0.x; acc[0][1] += a0*b0.y; acc[0][2] += a0*b0.z; acc[0][3] += a0*b0.w;
            acc[0][4] += a0*b1.x; acc[0][5] += a0*b1.y; acc[0][6] += a0*b1.z; acc[0][7] += a0*b1.w;
            acc[1][0] += a1*b0.x; acc[1][1] += a1*b0.y; acc[1][2] += a1*b0.z; acc[1][3] += a1*b0.w;
            acc[1][4] += a1*b1.x; acc[1][5] += a1*b1.y; acc[1][6] += a1*b1.z; acc[1][7] += a1*b1.w;
            acc[2][0] += a2*b0.x; acc[2][1] += a2*b0.y; acc[2][2] += a2*b0.z; acc[2][3] += a2*b0.w;
            acc[2][4] += a2*b1.x; acc[2][5] += a2*b1.y; acc[2][6] += a2*b1.z; acc[2][7] += a2*b1.w;
            acc[3][0] += a3*b0.x; acc[3][1] += a3*b0.y; acc[3][2] += a3*b0.z; acc[3][3] += a3*b0.w;
            acc[3][4] += a3*b1.x; acc[3][5] += a3*b1.y; acc[3][6] += a3*b1.z; acc[3][7] += a3*b1.w;
        }
        __syncthreads();
    }

    size_t pbase = ((size_t)blockIdx.y*MTOT + mbase + m0)*64 + n0;
    #pragma unroll
    for (int i = 0; i < 4; i++) {
        float4 w0 = make_float4(acc[i][0], acc[i][1], acc[i][2], acc[i][3]);
        float4 w1 = make_float4(acc[i][4], acc[i][5], acc[i][6], acc[i][7]);
        *(float4*)&g_encp[pbase + (size_t)i*64]     = w0;
        *(float4*)&g_encp[pbase + (size_t)i*64 + 4] = w1;
    }
}

// ================= K5: reduce partials + zi sample/kl + dec GEMM + small*c_few ============
__global__ void k5_zi_dec(const float* __restrict__ epszi,
                          const float* __restrict__ wdec,
                          const float* __restrict__ bdec,
                          const float* __restrict__ benc,
                          float* __restrict__ out)
{
    int m = blockIdx.x, t = threadIdx.x;
    __shared__ float zsh[ZID];
    __shared__ float ench[64];
    __shared__ float red[4][64];
    {
        int c = t & 63, part = t >> 6;
        float s = 0.0f;
        int lo = part*24 + min(part,2);   // 25,25,24,24 split of 98
        int hi = lo + ((part < 2) ? 25 : 24);
        for (int sp = lo; sp < hi; sp++)
            s += g_encp[((size_t)sp*MTOT + m)*64 + c];
        red[part][c] = s;
    }
    __syncthreads();
    if (t < 64) ench[t] = benc[t] + red[0][t] + red[1][t] + red[2][t] + red[3][t];
    __syncthreads();
    if (t < ZID) {
        float mu = ench[t];
        float sp = ench[32 + t];
        float sd = softplusf_(sp) + 1e-4f;
        float s  = mu + sd * epszi[m*ZID + t];
        float kl = 0.5f*(mu*mu + sd*sd) - logf(sd) - 0.5f;
        out[OFF_ZIS + m*ZID + t] = s;
        out[OFF_ZIK + m*ZID + t] = kl;
        zsh[t] = s;
    }
    __syncthreads();
    float cf = g_cf[m];
    for (int f = t; f < SMALLF; f += 256) {
        const float4* wr = (const float4*)(wdec + (size_t)f*ZID);
        float acc = bdec[f];
        #pragma unroll
        for (int q = 0; q < 8; q++) {
            float4 w4 = wr[q];
            acc += w4.x*zsh[q*4+0] + w4.y*zsh[q*4+1]
                 + w4.z*zsh[q*4+2] + w4.w*zsh[q*4+3];
        }
        float r = (f < 784) ? softplusf_(acc) : sigmoidf_(acc);
        g_smallw[m*SMALLF + f] = r * cf;
    }
}

// ================= K67: fully fused uncrop + k-reduction -> big_mask, big_mask_non, big_img
// grid: BATCH x 64 tiles of 256 pixels; 256 threads, 1 pixel each.
// tanh + bilinear sampling only for in-box (k,pixel) pairs (~10%); zeros elsewhere.
__global__ void __launch_bounds__(256) k67_all(float* __restrict__ out)
{
    int blk = blockIdx.x;
    int b = blk >> 6;
    int tile = blk & 63;
    int t = threadIdx.x;
    __shared__ float ssx[KOBJ], sox[KOBJ], ssy[KOBJ], soy[KOBJ];
    if (t < KOBJ) {
        int m = t*BATCH + b;
        float bx = g_bxf[m], bw = g_bwf[m];
        float by = g_byf[m], bh = g_bhf[m];
        float sx = 28.0f / bw;
        float sy = 28.0f / bh;
        ssx[t] = sx;  sox[t] = (0.5f - bx + 0.5f*bw)*sx - 0.5f;
        ssy[t] = sy;  soy[t] = (0.5f - by + 0.5f*bh)*sy - 0.5f;
    }
    __syncthreads();

    int p = tile*256 + t;
    float Xf = (float)(p >> 7);
    float Yf = (float)(p & 127);

    float v[KOBJ];
    float s = 0.0f;
    #pragma unroll
    for (int k = 0; k < KOBJ; k++) {
        float x = Xf*ssx[k] + sox[k];
        float y = Yf*ssy[k] + soy[k];
        float w = 0.0f, im = 0.0f, tw = 0.0f;
        if (x > -1.0f && x < 28.0f && y > -1.0f && y < 28.0f) {
            float x0f = floorf(x), y0f = floorf(y);
            int x0 = (int)x0f, y0 = (int)y0f;
            float wx1 = x - x0f, wy1 = y - y0f;
            float wx0 = 1.0f - wx1, wy0 = 1.0f - wy1;
            bool xa = (x0 >= 0), xb = (x0+1 < 28);
            bool ya = (y0 >= 0), yb = (y0+1 < 28);
            float w00 = (xa&&ya) ? wx0*wy0 : 0.0f;
            float w10 = (xb&&ya) ? wx1*wy0 : 0.0f;
            float w01 = (xa&&yb) ? wx0*wy1 : 0.0f;
            float w11 = (xb&&yb) ? wx1*wy1 : 0.0f;
            const float* img = &g_smallw[(size_t)(k*BATCH+b)*SMALLF];
            int i00 = max(x0,0)*28 + max(y0,0);
            // clamped indices with zeroed weights keep loads in-bounds
            int ix0 = min(max(x0,  0),27), ix1 = min(max(x0+1,0),27);
            int iy0 = min(max(y0,  0),27), iy1 = min(max(y0+1,0),27);
            int a00 = ix0*28+iy0, a10 = ix1*28+iy0, a01 = ix0*28+iy1, a11 = ix1*28+iy1;
            (void)i00;
            w  = w00*__ldg(&img[a00])     + w10*__ldg(&img[a10])
               + w01*__ldg(&img[a01])     + w11*__ldg(&img[a11]);
            im = w00*__ldg(&img[784+a00]) + w10*__ldg(&img[784+a10])
               + w01*__ldg(&img[784+a01]) + w11*__ldg(&img[784+a11]);
            tw = tanhf(w);
        }
        v[k] = w;
        s += w;
        out[OFF_BMNON + (size_t)(k*BATCH+b)*PIX + p] = tw;
        out[OFF_BIMG  + (size_t)(k*BATCH+b)*PIX + p] = im;
    }
    float ts = tanhf(s);
    float inv = 1.0f / fmaxf(s, 1e-6f);
    float f = ts * inv;
    #pragma unroll
    for (int k = 0; k < KOBJ; k++)
        out[OFF_BMASK + (size_t)(k*BATCH+b)*PIX + p] = v[k] * f;
}

// ================= launcher =================
extern "C" void kernel_launch(void* const* d_in, const int* in_sizes, int n_in,
                              void* d_out, int out_size)
{
    const float* logit = (const float*)d_in[0];
    const float* zmu   = (const float*)d_in[1];
    const float* zstd  = (const float*)d_in[2];
    const float* zeps  = (const float*)d_in[3];
    const float* epszi = (const float*)d_in[4];
    const float* feat  = (const float*)d_in[5];
    const float* wz    = (const float*)d_in[6];
    const float* bz    = (const float*)d_in[7];
    const float* wenc  = (const float*)d_in[8];
    const float* benc  = (const float*)d_in[9];
    const float* wdec  = (const float*)d_in[10];
    const float* bdec  = (const float*)d_in[11];
    float* out = (float*)d_out;

    k1_site<<<32, 256>>>(logit, zmu, zstd, zeps, wz, bz, out);
    k2_topk<<<BATCH, 1024>>>(out);
    k3_crop<<<MTOT, 256>>>(feat);
    dim3 g4(3, NSPLIT);
    k4_gemm<<<g4, 256>>>(wenc);
    k5_zi_dec<<<MTOT, 256>>>(epszi, wdec, bdec, benc, out);
    k67_all<<<BATCH*64, 256>>>(out);
}